// round 1
// baseline (speedup 1.0000x reference)
#include <cuda_runtime.h>
#include <math.h>

#define Bb   16
#define Mt   16
#define Dd   512
#define Ne   16
#define Hh   682
#define NHt  (Ne*Hh)      /* 10912 */
#define Rows (Bb*Mt)      /* 256   */
#define OUTD 512
#define YSPLIT 8
#define OSPLIT 32

// ---------------- scratch (device globals; no allocs allowed) ----------------
__device__ float g_logits[Rows*NHt];
__device__ float g_Dw[Rows*NHt];
__device__ float g_Cw[Rows*NHt];
__device__ float g_XW1[Rows*NHt];
__device__ float g_G[Rows*NHt];
__device__ float g_Ypart[YSPLIT*Rows*OUTD];
__device__ float g_Y[Rows*OUTD];
__device__ float g_b2sum[OUTD];
__device__ float g_opart[OSPLIT*Bb*OUTD];

// ---------------- tiled fp32 GEMM: C[Mr,Nc] = A[Mr,K] @ B ----------------
// MODE 0: B is row-major [K, Nc]
// MODE 1: B[k][j] = W1[(j/Hh)*K*Hh + k*Hh + (j%Hh)]   (W1 is [N,D,H])
// nsplit>1: write partials at C + z*Mr*Nc (z = blockIdx.z)
template<int MODE>
__global__ void gemm64(const float* __restrict__ A, const float* __restrict__ Bm,
                       float* __restrict__ C, int Mr, int Nc, int K, int nsplit)
{
    __shared__ float As[16][65];
    __shared__ float Bs[16][64];
    const int tid = threadIdx.x;
    const int tx = tid & 15, ty = tid >> 4;
    const int m0 = blockIdx.y * 64;
    const int j0 = blockIdx.x * 64;
    const int z  = blockIdx.z;
    const int ktiles = K >> 4;
    const int kt0 = (int)((long long)ktiles * z / nsplit);
    const int kt1 = (int)((long long)ktiles * (z + 1) / nsplit);

    const int arow = tid >> 2, ac4 = tid & 3;
    const int brow = tid >> 4, bc4 = tid & 15;

    float acc[4][4] = {};

    for (int kt = kt0; kt < kt1; ++kt) {
        const int k0 = kt << 4;
        // A tile (64 rows x 16 cols), one float4 per thread, stored transposed
        float4 av = *(const float4*)(A + (m0 + arow) * K + k0 + ac4 * 4);
        As[ac4*4 + 0][arow] = av.x;
        As[ac4*4 + 1][arow] = av.y;
        As[ac4*4 + 2][arow] = av.z;
        As[ac4*4 + 3][arow] = av.w;
        // B tile (16 rows x 64 cols), one float4 per thread
        const int j = j0 + bc4 * 4;
        if (MODE == 0) {
            float4 bv = make_float4(0.f, 0.f, 0.f, 0.f);
            if (j < Nc) bv = *(const float4*)(Bm + (k0 + brow) * Nc + j);
            Bs[brow][bc4*4 + 0] = bv.x;
            Bs[brow][bc4*4 + 1] = bv.y;
            Bs[brow][bc4*4 + 2] = bv.z;
            Bs[brow][bc4*4 + 3] = bv.w;
        } else {
            #pragma unroll
            for (int i = 0; i < 4; ++i) {
                const int jj = j + i;
                float v = 0.f;
                if (jj < Nc) {
                    const int n = jj / Hh;
                    const int h = jj - n * Hh;
                    v = Bm[(n * K + k0 + brow) * Hh + h];
                }
                Bs[brow][bc4*4 + i] = v;
            }
        }
        __syncthreads();
        #pragma unroll
        for (int k = 0; k < 16; ++k) {
            float a[4], bq[4];
            #pragma unroll
            for (int i = 0; i < 4; ++i) a[i]  = As[k][ty*4 + i];
            #pragma unroll
            for (int i = 0; i < 4; ++i) bq[i] = Bs[k][tx*4 + i];
            #pragma unroll
            for (int i = 0; i < 4; ++i)
                #pragma unroll
                for (int jx = 0; jx < 4; ++jx)
                    acc[i][jx] = fmaf(a[i], bq[jx], acc[i][jx]);
        }
        __syncthreads();
    }

    float* Cw = C + (long long)z * Mr * Nc;
    #pragma unroll
    for (int i = 0; i < 4; ++i) {
        const int row = m0 + ty*4 + i;
        #pragma unroll
        for (int jx = 0; jx < 4; ++jx) {
            const int col = j0 + tx*4 + jx;
            if (col < Nc) Cw[row * Nc + col] = acc[i][jx];
        }
    }
}

// ---------------- Dw = softmax over m (axis=1) ----------------
__global__ void softmax_m(const float* __restrict__ L, float* __restrict__ Dw)
{
    const int idx = blockIdx.x * blockDim.x + threadIdx.x;   // over B*N*H
    if (idx >= Bb * Ne * Hh) return;
    const int p = idx % Hh;
    const int n = (idx / Hh) % Ne;
    const int b = idx / (Hh * Ne);
    const int base = ((b * Mt) * Ne + n) * Hh + p;

    float v[Mt];
    float mx = -3.4e38f;
    #pragma unroll
    for (int m = 0; m < Mt; ++m) { v[m] = L[base + m * NHt]; mx = fmaxf(mx, v[m]); }
    float s = 0.f;
    #pragma unroll
    for (int m = 0; m < Mt; ++m) { v[m] = expf(v[m] - mx); s += v[m]; }
    const float inv = 1.f / s;
    #pragma unroll
    for (int m = 0; m < Mt; ++m) Dw[base + m * NHt] = v[m] * inv;
}

// ---------------- Cw = softmax_p( softmax_n(logits) ), one block per (b,m) ----------------
__global__ void softmax_np(const float* __restrict__ L, float* __restrict__ Cw)
{
    __shared__ float s[Ne * 688];
    const int bm  = blockIdx.x;
    const int tid = threadIdx.x;
    const float* Lrow = L + bm * NHt;

    for (int idx = tid; idx < NHt; idx += 256) {
        const int n = idx / Hh, p = idx - n * Hh;
        s[n * 688 + p] = Lrow[idx];
    }
    __syncthreads();

    // softmax over n (16 values) per p
    for (int p = tid; p < Hh; p += 256) {
        float mx = -3.4e38f;
        #pragma unroll
        for (int n = 0; n < Ne; ++n) mx = fmaxf(mx, s[n * 688 + p]);
        float sum = 0.f;
        #pragma unroll
        for (int n = 0; n < Ne; ++n) {
            const float e = expf(s[n * 688 + p] - mx);
            s[n * 688 + p] = e;
            sum += e;
        }
        const float inv = 1.f / sum;
        #pragma unroll
        for (int n = 0; n < Ne; ++n) s[n * 688 + p] *= inv;
    }
    __syncthreads();

    // softmax over p (682) per n: one warp per row, 8 warps x 2 rows
    const int warp = tid >> 5, lane = tid & 31;
    for (int n = warp; n < Ne; n += 8) {
        float mx = -3.4e38f;
        for (int p = lane; p < Hh; p += 32) mx = fmaxf(mx, s[n * 688 + p]);
        #pragma unroll
        for (int o = 16; o; o >>= 1) mx = fmaxf(mx, __shfl_xor_sync(0xffffffffu, mx, o));
        float sum = 0.f;
        for (int p = lane; p < Hh; p += 32) {
            const float e = expf(s[n * 688 + p] - mx);
            s[n * 688 + p] = e;
            sum += e;
        }
        #pragma unroll
        for (int o = 16; o; o >>= 1) sum += __shfl_xor_sync(0xffffffffu, sum, o);
        const float inv = 1.f / sum;
        for (int p = lane; p < Hh; p += 32)
            Cw[bm * NHt + n * Hh + p] = s[n * 688 + p] * inv;
    }
}

// ---------------- b2sum[d] = sum_n b2[n,d] ----------------
__global__ void b2sum_k(const float* __restrict__ b2, float* __restrict__ b2s)
{
    const int d = blockIdx.x * blockDim.x + threadIdx.x;
    if (d < OUTD) {
        float s = 0.f;
        #pragma unroll
        for (int n = 0; n < Ne; ++n) s += b2[n * OUTD + d];
        b2s[d] = s;
    }
}

// ---------------- fused mix -> relu -> combine ----------------
// Per (b,n):  G[b,m',n,h] = sum_p Cw[b,m',n,p] * relu( sum_m Dw[b,m,n,p]*XW1[b,m,n,h] + b1[n,h] )
// XW1 rows and G accumulators held in registers; Dw/Cw staged per-p-chunk in smem (broadcast reads).
__global__ __launch_bounds__(256) void fused_G(const float* __restrict__ XW1,
                                               const float* __restrict__ Dw,
                                               const float* __restrict__ Cwp,
                                               const float* __restrict__ b1,
                                               float* __restrict__ G)
{
    constexpr int PC = 128;
    __shared__ float ds[Mt][PC];
    __shared__ float cs[Mt][PC];

    const int bx = blockIdx.x;
    const int n  = bx & (Ne - 1);
    const int b  = bx >> 4;
    const int tid = threadIdx.x;

    const int h0 = tid, h1 = tid + 256, h2 = tid + 512;
    const bool v3 = (h2 < Hh);

    float xw0[Mt], xw1[Mt], xw2[Mt];
    #pragma unroll
    for (int m = 0; m < Mt; ++m) {
        const int base = ((b * Mt + m) * Ne + n) * Hh;
        xw0[m] = XW1[base + h0];
        xw1[m] = XW1[base + h1];
        xw2[m] = v3 ? XW1[base + h2] : 0.f;
    }
    const float bb0 = b1[n * Hh + h0];
    const float bb1 = b1[n * Hh + h1];
    const float bb2 = v3 ? b1[n * Hh + h2] : 0.f;

    float acc0[Mt] = {}, acc1[Mt] = {}, acc2[Mt] = {};

    for (int p0 = 0; p0 < Hh; p0 += PC) {
        const int pc = min(PC, Hh - p0);
        __syncthreads();
        for (int idx = tid; idx < Mt * PC; idx += 256) {
            const int m = idx / PC, pp = idx - m * PC;
            if (pp < pc) {
                const int a = ((b * Mt + m) * Ne + n) * Hh + p0 + pp;
                ds[m][pp] = Dw[a];
                cs[m][pp] = Cwp[a];
            }
        }
        __syncthreads();
        for (int pp = 0; pp < pc; ++pp) {
            float r0 = 0.f, r1 = 0.f, r2 = 0.f;
            #pragma unroll
            for (int m = 0; m < Mt; ++m) {
                const float d = ds[m][pp];
                r0 = fmaf(d, xw0[m], r0);
                r1 = fmaf(d, xw1[m], r1);
                r2 = fmaf(d, xw2[m], r2);
            }
            r0 = fmaxf(r0 + bb0, 0.f);
            r1 = fmaxf(r1 + bb1, 0.f);
            r2 = fmaxf(r2 + bb2, 0.f);
            #pragma unroll
            for (int m = 0; m < Mt; ++m) {
                const float c = cs[m][pp];
                acc0[m] = fmaf(c, r0, acc0[m]);
                acc1[m] = fmaf(c, r1, acc1[m]);
                acc2[m] = fmaf(c, r2, acc2[m]);
            }
        }
    }

    #pragma unroll
    for (int m = 0; m < Mt; ++m) {
        const int base = ((b * Mt + m) * Ne + n) * Hh;
        G[base + h0] = acc0[m];
        G[base + h1] = acc1[m];
        if (v3) G[base + h2] = acc2[m];
    }
}

// ---------------- reduce split-K partials for Y, add b2sum ----------------
__global__ void ypart_reduce(const float* __restrict__ part, const float* __restrict__ b2s,
                             float* __restrict__ Y)
{
    const int idx = blockIdx.x * blockDim.x + threadIdx.x;   // Rows*OUTD
    const int col = idx & (OUTD - 1);
    float s = b2s[col];
    #pragma unroll
    for (int z = 0; z < YSPLIT; ++z) s += part[z * (Rows * OUTD) + idx];
    Y[idx] = s;
}

// ---------------- output GEMM: out[16,512] = Yflat[16,8192] @ Wout + bout ----------------
__global__ void out_partial(const float* __restrict__ Y, const float* __restrict__ Wout,
                            float* __restrict__ part)
{
    __shared__ float ys[Bb][256];
    const int tid = threadIdx.x;
    const int col = blockIdx.x * 256 + tid;
    const int k0  = blockIdx.y * 256;

    for (int idx = tid; idx < Bb * 256; idx += 256) {
        const int bi = idx >> 8, kk = idx & 255;
        ys[bi][kk] = Y[bi * (Mt * Dd) + k0 + kk];
    }
    __syncthreads();

    float acc[Bb] = {};
    for (int kk = 0; kk < 256; ++kk) {
        const float w = Wout[(k0 + kk) * OUTD + col];
        #pragma unroll
        for (int bi = 0; bi < Bb; ++bi) acc[bi] = fmaf(ys[bi][kk], w, acc[bi]);
    }
    #pragma unroll
    for (int bi = 0; bi < Bb; ++bi)
        part[(blockIdx.y * Bb + bi) * OUTD + col] = acc[bi];
}

__global__ void out_reduce(const float* __restrict__ part, const float* __restrict__ bout,
                           float* __restrict__ out)
{
    const int idx = blockIdx.x * blockDim.x + threadIdx.x;   // Bb*OUTD = 8192
    const int col = idx & (OUTD - 1);
    const int bi  = idx >> 9;
    float s = bout[col];
    #pragma unroll
    for (int z = 0; z < OSPLIT; ++z) s += part[(z * Bb + bi) * OUTD + col];
    out[idx] = s;
}

// ---------------- launch ----------------
extern "C" void kernel_launch(void* const* d_in, const int* in_sizes, int n_in,
                              void* d_out, int out_size)
{
    const float* x    = (const float*)d_in[0];
    const float* phi  = (const float*)d_in[1];
    const float* W1   = (const float*)d_in[2];
    const float* b1   = (const float*)d_in[3];
    const float* W2   = (const float*)d_in[4];
    const float* b2   = (const float*)d_in[5];
    const float* Wout = (const float*)d_in[6];
    const float* bout = (const float*)d_in[7];
    float* out = (float*)d_out;

    float *p_logits, *p_Dw, *p_Cw, *p_XW1, *p_G, *p_Ypart, *p_Y, *p_b2sum, *p_opart;
    cudaGetSymbolAddress((void**)&p_logits, g_logits);
    cudaGetSymbolAddress((void**)&p_Dw,     g_Dw);
    cudaGetSymbolAddress((void**)&p_Cw,     g_Cw);
    cudaGetSymbolAddress((void**)&p_XW1,    g_XW1);
    cudaGetSymbolAddress((void**)&p_G,      g_G);
    cudaGetSymbolAddress((void**)&p_Ypart,  g_Ypart);
    cudaGetSymbolAddress((void**)&p_Y,      g_Y);
    cudaGetSymbolAddress((void**)&p_b2sum,  g_b2sum);
    cudaGetSymbolAddress((void**)&p_opart,  g_opart);

    const dim3 gBig((NHt + 63) / 64, Rows / 64, 1);          // 171 x 4
    gemm64<0><<<gBig, 256>>>(x, phi, p_logits, Rows, NHt, Dd, 1);
    gemm64<1><<<gBig, 256>>>(x, W1,  p_XW1,    Rows, NHt, Dd, 1);

    softmax_m <<<(Bb * Ne * Hh) / 256, 256>>>(p_logits, p_Dw);
    softmax_np<<<Rows, 256>>>(p_logits, p_Cw);
    b2sum_k   <<<(OUTD + 255) / 256, 256>>>(b2, p_b2sum);

    fused_G<<<Bb * Ne, 256>>>(p_XW1, p_Dw, p_Cw, b1, p_G);

    const dim3 gY(OUTD / 64, Rows / 64, YSPLIT);             // 8 x 4 x 8
    gemm64<0><<<gY, 256>>>(p_G, W2, p_Ypart, Rows, OUTD, NHt, YSPLIT);
    ypart_reduce<<<(Rows * OUTD) / 256, 256>>>(p_Ypart, p_b2sum, p_Y);

    const dim3 gO(OUTD / 256, OSPLIT, 1);                    // 2 x 32
    out_partial<<<gO, 256>>>(p_Y, Wout, p_opart);
    out_reduce <<<(Bb * OUTD) / 256, 256>>>(p_opart, bout, out);
}

// round 2
// speedup vs baseline: 1.1151x; 1.1151x over previous
#include <cuda_runtime.h>
#include <math.h>

#define Bb   16
#define Mt   16
#define Dd   512
#define Ne   16
#define Hh   682
#define NHt  (Ne*Hh)      /* 10912 */
#define Rows (Bb*Mt)      /* 256   */
#define OUTD 512
#define YSPLIT 8
#define OSPLIT 32

typedef unsigned long long ull;

// ---- packed fp32 helpers (FFMA2 path: ptxas never emits, HW has it) ----
__device__ __forceinline__ ull pk2(float lo, float hi) {
    ull r; asm("mov.b64 %0,{%1,%2};" : "=l"(r) : "f"(lo), "f"(hi)); return r;
}
__device__ __forceinline__ void upk2(ull v, float& lo, float& hi) {
    asm("mov.b64 {%0,%1},%2;" : "=f"(lo), "=f"(hi) : "l"(v));
}
__device__ __forceinline__ ull fma2(ull a, ull b, ull c) {
    ull d; asm("fma.rn.f32x2 %0,%1,%2,%3;" : "=l"(d) : "l"(a), "l"(b), "l"(c)); return d;
}

// ---------------- scratch (device globals; no allocs allowed) ----------------
__device__ float g_logits[Rows*NHt];
__device__ float g_Dw[Rows*NHt];
__device__ float g_Cw[Rows*NHt];
__device__ float g_XW1[Rows*NHt];
__device__ float g_G[Rows*NHt];
__device__ float g_Ypart[YSPLIT*Rows*OUTD];
__device__ float g_Y[Rows*OUTD];
__device__ float g_b2sum[OUTD];
__device__ float g_opart[OSPLIT*Bb*OUTD];

// ---------------- tiled fp32 GEMM (f32x2 inner): C[Mr,Nc] = A[Mr,K] @ B ----------------
// MODE 0: B row-major [K, Nc]
// MODE 1: B[k][j] = W1[(j/Hh)*K*Hh + k*Hh + (j%Hh)]   (W1 is [N,D,H])
template<int MODE>
__global__ void gemm64(const float* __restrict__ A, const float* __restrict__ Bm,
                       float* __restrict__ C, int Mr, int Nc, int K, int nsplit)
{
    __shared__ __align__(16) float As[16][68];   // stride 68 keeps float4 alignment
    __shared__ __align__(16) float Bs[16][64];
    const int tid = threadIdx.x;
    const int tx = tid & 15, ty = tid >> 4;
    const int m0 = blockIdx.y * 64;
    const int j0 = blockIdx.x * 64;
    const int z  = blockIdx.z;
    const int ktiles = K >> 4;
    const int kt0 = (int)((long long)ktiles * z / nsplit);
    const int kt1 = (int)((long long)ktiles * (z + 1) / nsplit);

    const int arow = tid >> 2, ac4 = tid & 3;
    const int brow = tid >> 4, bc4 = tid & 15;

    ull acc[4][2] = {};   // rows i=0..3  x  col-pairs

    for (int kt = kt0; kt < kt1; ++kt) {
        const int k0 = kt << 4;
        // A tile (64 rows x 16 cols), one float4 per thread, stored transposed
        float4 av = *(const float4*)(A + (m0 + arow) * K + k0 + ac4 * 4);
        As[ac4*4 + 0][arow] = av.x;
        As[ac4*4 + 1][arow] = av.y;
        As[ac4*4 + 2][arow] = av.z;
        As[ac4*4 + 3][arow] = av.w;
        // B tile (16 rows x 64 cols)
        const int j = j0 + bc4 * 4;
        if (MODE == 0) {
            float4 bv = make_float4(0.f, 0.f, 0.f, 0.f);
            if (j < Nc) bv = *(const float4*)(Bm + (k0 + brow) * Nc + j);
            *(float4*)&Bs[brow][bc4*4] = bv;
        } else {
            #pragma unroll
            for (int i = 0; i < 4; ++i) {
                const int jj = j + i;
                float v = 0.f;
                if (jj < Nc) {
                    const int n = jj / Hh;
                    const int h = jj - n * Hh;
                    v = Bm[(n * K + k0 + brow) * Hh + h];
                }
                Bs[brow][bc4*4 + i] = v;
            }
        }
        __syncthreads();
        #pragma unroll
        for (int k = 0; k < 16; ++k) {
            float4 a4 = *(const float4*)&As[k][ty*4];
            float4 b4 = *(const float4*)&Bs[k][tx*4];
            const ull bp0 = pk2(b4.x, b4.y);
            const ull bp1 = pk2(b4.z, b4.w);
            const ull ad0 = pk2(a4.x, a4.x);
            const ull ad1 = pk2(a4.y, a4.y);
            const ull ad2 = pk2(a4.z, a4.z);
            const ull ad3 = pk2(a4.w, a4.w);
            acc[0][0] = fma2(ad0, bp0, acc[0][0]);  acc[0][1] = fma2(ad0, bp1, acc[0][1]);
            acc[1][0] = fma2(ad1, bp0, acc[1][0]);  acc[1][1] = fma2(ad1, bp1, acc[1][1]);
            acc[2][0] = fma2(ad2, bp0, acc[2][0]);  acc[2][1] = fma2(ad2, bp1, acc[2][1]);
            acc[3][0] = fma2(ad3, bp0, acc[3][0]);  acc[3][1] = fma2(ad3, bp1, acc[3][1]);
        }
        __syncthreads();
    }

    float* Cw = C + (long long)z * Mr * Nc;
    const int colb = j0 + tx*4;
    #pragma unroll
    for (int i = 0; i < 4; ++i) {
        const int row = m0 + ty*4 + i;
        float4 o;
        upk2(acc[i][0], o.x, o.y);
        upk2(acc[i][1], o.z, o.w);
        if (colb < Nc) *(float4*)(Cw + row * Nc + colb) = o;
    }
}

// ---------------- Dw = softmax over m (axis=1) ----------------
__global__ void softmax_m(const float* __restrict__ L, float* __restrict__ Dw)
{
    const int idx = blockIdx.x * blockDim.x + threadIdx.x;   // over B*N*H
    if (idx >= Bb * Ne * Hh) return;
    const int p = idx % Hh;
    const int n = (idx / Hh) % Ne;
    const int b = idx / (Hh * Ne);
    const int base = ((b * Mt) * Ne + n) * Hh + p;

    float v[Mt];
    float mx = -3.4e38f;
    #pragma unroll
    for (int m = 0; m < Mt; ++m) { v[m] = L[base + m * NHt]; mx = fmaxf(mx, v[m]); }
    float s = 0.f;
    #pragma unroll
    for (int m = 0; m < Mt; ++m) { v[m] = expf(v[m] - mx); s += v[m]; }
    const float inv = 1.f / s;
    #pragma unroll
    for (int m = 0; m < Mt; ++m) Dw[base + m * NHt] = v[m] * inv;
}

// ---------------- Cw = softmax_p( softmax_n(logits) ), one block per (b,m) ----------------
__global__ void softmax_np(const float* __restrict__ L, float* __restrict__ Cw)
{
    __shared__ float s[Ne * 688];
    const int bm  = blockIdx.x;
    const int tid = threadIdx.x;
    const float* Lrow = L + bm * NHt;

    for (int idx = tid; idx < NHt; idx += 256) {
        const int n = idx / Hh, p = idx - n * Hh;
        s[n * 688 + p] = Lrow[idx];
    }
    __syncthreads();

    for (int p = tid; p < Hh; p += 256) {
        float mx = -3.4e38f;
        #pragma unroll
        for (int n = 0; n < Ne; ++n) mx = fmaxf(mx, s[n * 688 + p]);
        float sum = 0.f;
        #pragma unroll
        for (int n = 0; n < Ne; ++n) {
            const float e = expf(s[n * 688 + p] - mx);
            s[n * 688 + p] = e;
            sum += e;
        }
        const float inv = 1.f / sum;
        #pragma unroll
        for (int n = 0; n < Ne; ++n) s[n * 688 + p] *= inv;
    }
    __syncthreads();

    const int warp = tid >> 5, lane = tid & 31;
    for (int n = warp; n < Ne; n += 8) {
        float mx = -3.4e38f;
        for (int p = lane; p < Hh; p += 32) mx = fmaxf(mx, s[n * 688 + p]);
        #pragma unroll
        for (int o = 16; o; o >>= 1) mx = fmaxf(mx, __shfl_xor_sync(0xffffffffu, mx, o));
        float sum = 0.f;
        for (int p = lane; p < Hh; p += 32) {
            const float e = expf(s[n * 688 + p] - mx);
            s[n * 688 + p] = e;
            sum += e;
        }
        #pragma unroll
        for (int o = 16; o; o >>= 1) sum += __shfl_xor_sync(0xffffffffu, sum, o);
        const float inv = 1.f / sum;
        for (int p = lane; p < Hh; p += 32)
            Cw[bm * NHt + n * Hh + p] = s[n * 688 + p] * inv;
    }
}

// ---------------- b2sum[d] = sum_n b2[n,d] ----------------
__global__ void b2sum_k(const float* __restrict__ b2, float* __restrict__ b2s)
{
    const int d = blockIdx.x * blockDim.x + threadIdx.x;
    if (d < OUTD) {
        float s = 0.f;
        #pragma unroll
        for (int n = 0; n < Ne; ++n) s += b2[n * OUTD + d];
        b2s[d] = s;
    }
}

// ---------------- fused mix -> relu -> combine (f32x2, paired over m) ----------------
// Per (b,n):  G[b,m',n,h] = sum_p Cw[b,m',n,p] * relu( sum_m Dw[b,m,n,p]*XW1[b,m,n,h] + b1[n,h] )
__global__ __launch_bounds__(256, 2) void fused_G(const float* __restrict__ XW1,
                                                  const float* __restrict__ Dw,
                                                  const float* __restrict__ Cwp,
                                                  const float* __restrict__ b1,
                                                  float* __restrict__ G)
{
    constexpr int PC = 128;
    // [pp][m] layout, stride 18 (even -> 8B alignment for pair loads; conflict-light stores)
    __shared__ __align__(16) float ds[PC][18];
    __shared__ __align__(16) float cs[PC][18];

    const int bx = blockIdx.x;
    const int n  = bx & (Ne - 1);
    const int b  = bx >> 4;
    const int tid = threadIdx.x;

    const int h0 = tid, h1 = tid + 256, h2 = tid + 512;
    const bool v3 = (h2 < Hh);

    // XW1 rows packed over m-pairs: lane0 = m even, lane1 = m odd
    ull xw0p[8], xw1p[8], xw2p[8];
    #pragma unroll
    for (int mp = 0; mp < 8; ++mp) {
        const int be = ((b * Mt + 2*mp    ) * Ne + n) * Hh;
        const int bo = ((b * Mt + 2*mp + 1) * Ne + n) * Hh;
        xw0p[mp] = pk2(XW1[be + h0], XW1[bo + h0]);
        xw1p[mp] = pk2(XW1[be + h1], XW1[bo + h1]);
        xw2p[mp] = v3 ? pk2(XW1[be + h2], XW1[bo + h2]) : 0ULL;
    }
    const float bb0 = b1[n * Hh + h0];
    const float bb1 = b1[n * Hh + h1];
    const float bb2 = v3 ? b1[n * Hh + h2] : 0.f;

    ull acc0[8] = {}, acc1[8] = {}, acc2[8] = {};

    for (int p0 = 0; p0 < Hh; p0 += PC) {
        const int pc = min(PC, Hh - p0);
        __syncthreads();
        // loader: coalesced over pp (global), writes transposed [pp][m]
        for (int idx = tid; idx < Mt * PC; idx += 256) {
            const int pp = idx & (PC - 1);
            const int m  = idx >> 7;
            if (pp < pc) {
                const int a = ((b * Mt + m) * Ne + n) * Hh + p0 + pp;
                ds[pp][m] = Dw[a];
                cs[pp][m] = Cwp[a];
            }
        }
        __syncthreads();
        for (int pp = 0; pp < pc; ++pp) {
            // r = sum_m d[m]*xw[m]  (paired over m, cross-lane add at end)
            ull r0 = 0ULL, r1 = 0ULL, r2 = 0ULL;
            #pragma unroll
            for (int mp = 0; mp < 8; ++mp) {
                const ull dp = *(const ull*)&ds[pp][2*mp];
                r0 = fma2(dp, xw0p[mp], r0);
                r1 = fma2(dp, xw1p[mp], r1);
                r2 = fma2(dp, xw2p[mp], r2);
            }
            float lo, hi, s0, s1, s2;
            upk2(r0, lo, hi); s0 = fmaxf(lo + hi + bb0, 0.f);
            upk2(r1, lo, hi); s1 = fmaxf(lo + hi + bb1, 0.f);
            upk2(r2, lo, hi); s2 = fmaxf(lo + hi + bb2, 0.f);
            const ull s0d = pk2(s0, s0);
            const ull s1d = pk2(s1, s1);
            const ull s2d = pk2(s2, s2);
            // acc[m] += c[m]*s  (paired over m; c pair shared across the 3 h's)
            #pragma unroll
            for (int mp = 0; mp < 8; ++mp) {
                const ull cp = *(const ull*)&cs[pp][2*mp];
                acc0[mp] = fma2(cp, s0d, acc0[mp]);
                acc1[mp] = fma2(cp, s1d, acc1[mp]);
                acc2[mp] = fma2(cp, s2d, acc2[mp]);
            }
        }
    }

    #pragma unroll
    for (int mp = 0; mp < 8; ++mp) {
        const int be = ((b * Mt + 2*mp    ) * Ne + n) * Hh;
        const int bo = ((b * Mt + 2*mp + 1) * Ne + n) * Hh;
        float lo, hi;
        upk2(acc0[mp], lo, hi); G[be + h0] = lo; G[bo + h0] = hi;
        upk2(acc1[mp], lo, hi); G[be + h1] = lo; G[bo + h1] = hi;
        if (v3) { upk2(acc2[mp], lo, hi); G[be + h2] = lo; G[bo + h2] = hi; }
    }
}

// ---------------- reduce split-K partials for Y, add b2sum ----------------
__global__ void ypart_reduce(const float* __restrict__ part, const float* __restrict__ b2s,
                             float* __restrict__ Y)
{
    const int idx = blockIdx.x * blockDim.x + threadIdx.x;   // Rows*OUTD
    const int col = idx & (OUTD - 1);
    float s = b2s[col];
    #pragma unroll
    for (int z = 0; z < YSPLIT; ++z) s += part[z * (Rows * OUTD) + idx];
    Y[idx] = s;
}

// ---------------- output GEMM: out[16,512] = Yflat[16,8192] @ Wout + bout ----------------
__global__ void out_partial(const float* __restrict__ Y, const float* __restrict__ Wout,
                            float* __restrict__ part)
{
    __shared__ float ys[Bb][256];
    const int tid = threadIdx.x;
    const int col = blockIdx.x * 256 + tid;
    const int k0  = blockIdx.y * 256;

    for (int idx = tid; idx < Bb * 256; idx += 256) {
        const int bi = idx >> 8, kk = idx & 255;
        ys[bi][kk] = Y[bi * (Mt * Dd) + k0 + kk];
    }
    __syncthreads();

    float acc[Bb] = {};
    for (int kk = 0; kk < 256; ++kk) {
        const float w = Wout[(k0 + kk) * OUTD + col];
        #pragma unroll
        for (int bi = 0; bi < Bb; ++bi) acc[bi] = fmaf(ys[bi][kk], w, acc[bi]);
    }
    #pragma unroll
    for (int bi = 0; bi < Bb; ++bi)
        part[(blockIdx.y * Bb + bi) * OUTD + col] = acc[bi];
}

__global__ void out_reduce(const float* __restrict__ part, const float* __restrict__ bout,
                           float* __restrict__ out)
{
    const int idx = blockIdx.x * blockDim.x + threadIdx.x;   // Bb*OUTD = 8192
    const int col = idx & (OUTD - 1);
    const int bi  = idx >> 9;
    float s = bout[col];
    #pragma unroll
    for (int z = 0; z < OSPLIT; ++z) s += part[(z * Bb + bi) * OUTD + col];
    out[idx] = s;
}

// ---------------- launch ----------------
extern "C" void kernel_launch(void* const* d_in, const int* in_sizes, int n_in,
                              void* d_out, int out_size)
{
    const float* x    = (const float*)d_in[0];
    const float* phi  = (const float*)d_in[1];
    const float* W1   = (const float*)d_in[2];
    const float* b1   = (const float*)d_in[3];
    const float* W2   = (const float*)d_in[4];
    const float* b2   = (const float*)d_in[5];
    const float* Wout = (const float*)d_in[6];
    const float* bout = (const float*)d_in[7];
    float* out = (float*)d_out;

    float *p_logits, *p_Dw, *p_Cw, *p_XW1, *p_G, *p_Ypart, *p_Y, *p_b2sum, *p_opart;
    cudaGetSymbolAddress((void**)&p_logits, g_logits);
    cudaGetSymbolAddress((void**)&p_Dw,     g_Dw);
    cudaGetSymbolAddress((void**)&p_Cw,     g_Cw);
    cudaGetSymbolAddress((void**)&p_XW1,    g_XW1);
    cudaGetSymbolAddress((void**)&p_G,      g_G);
    cudaGetSymbolAddress((void**)&p_Ypart,  g_Ypart);
    cudaGetSymbolAddress((void**)&p_Y,      g_Y);
    cudaGetSymbolAddress((void**)&p_b2sum,  g_b2sum);
    cudaGetSymbolAddress((void**)&p_opart,  g_opart);

    const dim3 gBig((NHt + 63) / 64, Rows / 64, 1);          // 171 x 4
    gemm64<0><<<gBig, 256>>>(x, phi, p_logits, Rows, NHt, Dd, 1);
    gemm64<1><<<gBig, 256>>>(x, W1,  p_XW1,    Rows, NHt, Dd, 1);

    softmax_m <<<(Bb * Ne * Hh + 255) / 256, 256>>>(p_logits, p_Dw);
    softmax_np<<<Rows, 256>>>(p_logits, p_Cw);
    b2sum_k   <<<(OUTD + 255) / 256, 256>>>(b2, p_b2sum);

    fused_G<<<Bb * Ne, 256>>>(p_XW1, p_Dw, p_Cw, b1, p_G);

    const dim3 gY(OUTD / 64, Rows / 64, YSPLIT);             // 8 x 4 x 8
    gemm64<0><<<gY, 256>>>(p_G, W2, p_Ypart, Rows, OUTD, NHt, YSPLIT);
    ypart_reduce<<<(Rows * OUTD) / 256, 256>>>(p_Ypart, p_b2sum, p_Y);

    const dim3 gO(OUTD / 256, OSPLIT, 1);                    // 2 x 32
    out_partial<<<gO, 256>>>(p_Y, Wout, p_opart);
    out_reduce <<<(Bb * OUTD) / 256, 256>>>(p_opart, bout, out);
}

// round 3
// speedup vs baseline: 1.2055x; 1.0810x over previous
#include <cuda_runtime.h>
#include <math.h>

#define Bb   16
#define Mt   16
#define Dd   512
#define Ne   16
#define Hh   682
#define NHt  (Ne*Hh)      /* 10912 */
#define Rows (Bb*Mt)      /* 256   */
#define OUTD 512
#define YSPLIT 16
#define OSPLIT 64

typedef unsigned long long ull;

// ---- packed fp32 helpers (FFMA2 via PTX fma.rn.f32x2) ----
__device__ __forceinline__ ull pk2(float lo, float hi) {
    ull r; asm("mov.b64 %0,{%1,%2};" : "=l"(r) : "f"(lo), "f"(hi)); return r;
}
__device__ __forceinline__ void upk2(ull v, float& lo, float& hi) {
    asm("mov.b64 {%0,%1},%2;" : "=f"(lo), "=f"(hi) : "l"(v));
}
__device__ __forceinline__ ull fma2(ull a, ull b, ull c) {
    ull d; asm("fma.rn.f32x2 %0,%1,%2,%3;" : "=l"(d) : "l"(a), "l"(b), "l"(c)); return d;
}

// ---------------- scratch ----------------
__device__ float g_logits[Rows*NHt];
__device__ float g_Dw[Rows*NHt];
__device__ float g_Cw[Rows*NHt];
__device__ float g_XW1[Rows*NHt];
__device__ float g_G[Rows*NHt];
__device__ float g_Ypart[YSPLIT*Rows*OUTD];
__device__ float g_Y[Rows*OUTD];
__device__ float g_b2sum[OUTD];
__device__ float g_opart[OSPLIT*Bb*OUTD];

// ---------------- GEMM, 64x128 tile, 128 threads, 8x8/thread (f32x2) ----------------
// MODE 0: B row-major [K, Nc]
// MODE 1: B[k][j] = W1[n][k][h], j = n*Hh + h   (W1 is [N, K, Hh])
template<int MODE>
__global__ __launch_bounds__(128) void gemmT(const float* __restrict__ A,
                                             const float* __restrict__ Bm,
                                             float* __restrict__ C,
                                             int Mr, int Nc, int K, int nsplit)
{
    __shared__ __align__(16) float As[16][64];    // k-major (transposed A tile)
    __shared__ __align__(16) float Bs[16][128];
    const int tid = threadIdx.x;
    const int tx = tid & 15, ty = tid >> 4;       // tx: 16 col-groups of 8; ty: 8 row-groups of 8
    const int m0 = blockIdx.y * 64;
    const int j0 = blockIdx.x * 128;
    const int z  = blockIdx.z;
    const int ktiles = K >> 4;
    const int kt0 = (int)((long long)ktiles * z / nsplit);
    const int kt1 = (int)((long long)ktiles * (z + 1) / nsplit);

    // A load mapping: row = tid>>1 (0..63), half = tid&1 (cols 0..7 / 8..15)
    const int arow = tid >> 1, ahalf = tid & 1;
    // B load mapping: 4 float4 per thread over 512 float4 slots
    // MODE1 incremental (n,h) decomposition
    int bn[4], bh[4], brw[4], bc4[4];
    #pragma unroll
    for (int i = 0; i < 4; ++i) {
        const int f4 = tid + i * 128;
        brw[i] = f4 >> 5;
        bc4[i] = f4 & 31;
    }
    if (MODE == 1) {
        #pragma unroll
        for (int i = 0; i < 4; ++i) {
            const int j = j0 + bc4[i] * 4;
            int n = j / Hh;
            int h = j - n * Hh;
            bn[i] = n; bh[i] = h;
        }
    }

    ull acc[8][4] = {};   // 8 a-rows x 4 b-col-pairs

    for (int kt = kt0; kt < kt1; ++kt) {
        const int k0 = kt << 4;
        // ---- A tile: 64x16, transposed into As[k][m]
        {
            const float* ap = A + (m0 + arow) * K + k0 + ahalf * 8;
            float4 v0 = *(const float4*)(ap);
            float4 v1 = *(const float4*)(ap + 4);
            const int c0 = ahalf * 8;
            As[c0+0][arow] = v0.x; As[c0+1][arow] = v0.y;
            As[c0+2][arow] = v0.z; As[c0+3][arow] = v0.w;
            As[c0+4][arow] = v1.x; As[c0+5][arow] = v1.y;
            As[c0+6][arow] = v1.z; As[c0+7][arow] = v1.w;
        }
        // ---- B tile: 16x128
        #pragma unroll
        for (int i = 0; i < 4; ++i) {
            const int row = brw[i];
            const int j   = j0 + bc4[i] * 4;
            if (MODE == 0) {
                float4 bv = make_float4(0.f, 0.f, 0.f, 0.f);
                if (j < Nc) bv = *(const float4*)(Bm + (k0 + row) * Nc + j);
                *(float4*)&Bs[row][bc4[i]*4] = bv;
            } else {
                int n = bn[i], h = bh[i];
                #pragma unroll
                for (int e = 0; e < 4; ++e) {
                    float v = 0.f;
                    if (j + e < Nc) v = Bm[(n * K + k0 + row) * Hh + h];
                    Bs[row][bc4[i]*4 + e] = v;
                    if (++h >= Hh) { h = 0; ++n; }
                }
            }
        }
        __syncthreads();
        #pragma unroll
        for (int k = 0; k < 16; ++k) {
            float4 a0 = *(const float4*)&As[k][ty*8];
            float4 a1 = *(const float4*)&As[k][ty*8+4];
            float4 b0 = *(const float4*)&Bs[k][tx*8];
            float4 b1 = *(const float4*)&Bs[k][tx*8+4];
            ull bp[4];
            bp[0] = pk2(b0.x, b0.y); bp[1] = pk2(b0.z, b0.w);
            bp[2] = pk2(b1.x, b1.y); bp[3] = pk2(b1.z, b1.w);
            float ar[8] = {a0.x,a0.y,a0.z,a0.w,a1.x,a1.y,a1.z,a1.w};
            #pragma unroll
            for (int i = 0; i < 8; ++i) {
                const ull ad = pk2(ar[i], ar[i]);
                #pragma unroll
                for (int jj = 0; jj < 4; ++jj)
                    acc[i][jj] = fma2(ad, bp[jj], acc[i][jj]);
            }
        }
        __syncthreads();
    }

    float* Cw = C + (long long)z * Mr * Nc;
    const int colb = j0 + tx * 8;
    if (colb < Nc) {
        #pragma unroll
        for (int i = 0; i < 8; ++i) {
            const int row = m0 + ty * 8 + i;
            float4 o0, o1;
            upk2(acc[i][0], o0.x, o0.y); upk2(acc[i][1], o0.z, o0.w);
            upk2(acc[i][2], o1.x, o1.y); upk2(acc[i][3], o1.z, o1.w);
            *(float4*)(Cw + row * Nc + colb)     = o0;
            *(float4*)(Cw + row * Nc + colb + 4) = o1;
        }
    }
}

// ---------------- Dw = softmax over m (axis=1), float4 over columns ----------------
__global__ void softmax_m(const float* __restrict__ L, float* __restrict__ Dw)
{
    const int idx = blockIdx.x * blockDim.x + threadIdx.x;   // over Bb * NHt/4
    if (idx >= Bb * (NHt / 4)) return;
    const int b = idx / (NHt / 4);
    const int c = (idx - b * (NHt / 4)) * 4;
    const float* base = L + b * Mt * NHt + c;

    float4 v[Mt];
    float4 mx = make_float4(-3.4e38f, -3.4e38f, -3.4e38f, -3.4e38f);
    #pragma unroll
    for (int m = 0; m < Mt; ++m) {
        v[m] = *(const float4*)(base + m * NHt);
        mx.x = fmaxf(mx.x, v[m].x); mx.y = fmaxf(mx.y, v[m].y);
        mx.z = fmaxf(mx.z, v[m].z); mx.w = fmaxf(mx.w, v[m].w);
    }
    float4 s = make_float4(0.f, 0.f, 0.f, 0.f);
    #pragma unroll
    for (int m = 0; m < Mt; ++m) {
        v[m].x = expf(v[m].x - mx.x); s.x += v[m].x;
        v[m].y = expf(v[m].y - mx.y); s.y += v[m].y;
        v[m].z = expf(v[m].z - mx.z); s.z += v[m].z;
        v[m].w = expf(v[m].w - mx.w); s.w += v[m].w;
    }
    const float4 inv = make_float4(1.f/s.x, 1.f/s.y, 1.f/s.z, 1.f/s.w);
    float* ob = Dw + b * Mt * NHt + c;
    #pragma unroll
    for (int m = 0; m < Mt; ++m) {
        float4 o = make_float4(v[m].x*inv.x, v[m].y*inv.y, v[m].z*inv.z, v[m].w*inv.w);
        *(float4*)(ob + m * NHt) = o;
    }
}

// ---------------- Cw = softmax_p( softmax_n(logits) ) ----------------
__global__ void softmax_np(const float* __restrict__ L, float* __restrict__ Cw)
{
    __shared__ float s[Ne * 688];
    const int bm  = blockIdx.x;
    const int tid = threadIdx.x;
    const float* Lrow = L + bm * NHt;

    for (int idx = tid; idx < NHt; idx += 256) {
        const int n = idx / Hh, p = idx - n * Hh;
        s[n * 688 + p] = Lrow[idx];
    }
    __syncthreads();

    for (int p = tid; p < Hh; p += 256) {
        float mx = -3.4e38f;
        #pragma unroll
        for (int n = 0; n < Ne; ++n) mx = fmaxf(mx, s[n * 688 + p]);
        float sum = 0.f;
        #pragma unroll
        for (int n = 0; n < Ne; ++n) {
            const float e = expf(s[n * 688 + p] - mx);
            s[n * 688 + p] = e;
            sum += e;
        }
        const float inv = 1.f / sum;
        #pragma unroll
        for (int n = 0; n < Ne; ++n) s[n * 688 + p] *= inv;
    }
    __syncthreads();

    const int warp = tid >> 5, lane = tid & 31;
    for (int n = warp; n < Ne; n += 8) {
        float mx = -3.4e38f;
        for (int p = lane; p < Hh; p += 32) mx = fmaxf(mx, s[n * 688 + p]);
        #pragma unroll
        for (int o = 16; o; o >>= 1) mx = fmaxf(mx, __shfl_xor_sync(0xffffffffu, mx, o));
        float sum = 0.f;
        for (int p = lane; p < Hh; p += 32) {
            const float e = expf(s[n * 688 + p] - mx);
            s[n * 688 + p] = e;
            sum += e;
        }
        #pragma unroll
        for (int o = 16; o; o >>= 1) sum += __shfl_xor_sync(0xffffffffu, sum, o);
        const float inv = 1.f / sum;
        for (int p = lane; p < Hh; p += 32)
            Cw[bm * NHt + n * Hh + p] = s[n * 688 + p] * inv;
    }
}

// ---------------- b2sum ----------------
__global__ void b2sum_k(const float* __restrict__ b2, float* __restrict__ b2s)
{
    const int d = blockIdx.x * blockDim.x + threadIdx.x;
    if (d < OUTD) {
        float s = 0.f;
        #pragma unroll
        for (int n = 0; n < Ne; ++n) s += b2[n * OUTD + d];
        b2s[d] = s;
    }
}

// ---------------- fused mix -> relu -> combine (f32x2, paired over m) ----------------
__global__ __launch_bounds__(256, 2) void fused_G(const float* __restrict__ XW1,
                                                  const float* __restrict__ Dw,
                                                  const float* __restrict__ Cwp,
                                                  const float* __restrict__ b1,
                                                  float* __restrict__ G)
{
    constexpr int PC = 128;
    __shared__ __align__(16) float ds[PC][18];
    __shared__ __align__(16) float cs[PC][18];

    const int bx = blockIdx.x;
    const int n  = bx & (Ne - 1);
    const int b  = bx >> 4;
    const int tid = threadIdx.x;

    const int h0 = tid, h1 = tid + 256, h2 = tid + 512;
    const bool v3 = (h2 < Hh);

    ull xw0p[8], xw1p[8], xw2p[8];
    #pragma unroll
    for (int mp = 0; mp < 8; ++mp) {
        const int be = ((b * Mt + 2*mp    ) * Ne + n) * Hh;
        const int bo = ((b * Mt + 2*mp + 1) * Ne + n) * Hh;
        xw0p[mp] = pk2(XW1[be + h0], XW1[bo + h0]);
        xw1p[mp] = pk2(XW1[be + h1], XW1[bo + h1]);
        xw2p[mp] = v3 ? pk2(XW1[be + h2], XW1[bo + h2]) : 0ULL;
    }
    const float bb0 = b1[n * Hh + h0];
    const float bb1 = b1[n * Hh + h1];
    const float bb2 = v3 ? b1[n * Hh + h2] : 0.f;

    ull acc0[8] = {}, acc1[8] = {}, acc2[8] = {};

    for (int p0 = 0; p0 < Hh; p0 += PC) {
        const int pc = min(PC, Hh - p0);
        __syncthreads();
        for (int idx = tid; idx < Mt * PC; idx += 256) {
            const int pp = idx & (PC - 1);
            const int m  = idx >> 7;
            if (pp < pc) {
                const int a = ((b * Mt + m) * Ne + n) * Hh + p0 + pp;
                ds[pp][m] = Dw[a];
                cs[pp][m] = Cwp[a];
            }
        }
        __syncthreads();
        for (int pp = 0; pp < pc; ++pp) {
            ull r0 = 0ULL, r1 = 0ULL, r2 = 0ULL;
            #pragma unroll
            for (int mp = 0; mp < 8; ++mp) {
                const ull dp = *(const ull*)&ds[pp][2*mp];
                r0 = fma2(dp, xw0p[mp], r0);
                r1 = fma2(dp, xw1p[mp], r1);
                r2 = fma2(dp, xw2p[mp], r2);
            }
            float lo, hi, s0, s1, s2;
            upk2(r0, lo, hi); s0 = fmaxf(lo + hi + bb0, 0.f);
            upk2(r1, lo, hi); s1 = fmaxf(lo + hi + bb1, 0.f);
            upk2(r2, lo, hi); s2 = fmaxf(lo + hi + bb2, 0.f);
            const ull s0d = pk2(s0, s0);
            const ull s1d = pk2(s1, s1);
            const ull s2d = pk2(s2, s2);
            #pragma unroll
            for (int mp = 0; mp < 8; ++mp) {
                const ull cp = *(const ull*)&cs[pp][2*mp];
                acc0[mp] = fma2(cp, s0d, acc0[mp]);
                acc1[mp] = fma2(cp, s1d, acc1[mp]);
                acc2[mp] = fma2(cp, s2d, acc2[mp]);
            }
        }
    }

    #pragma unroll
    for (int mp = 0; mp < 8; ++mp) {
        const int be = ((b * Mt + 2*mp    ) * Ne + n) * Hh;
        const int bo = ((b * Mt + 2*mp + 1) * Ne + n) * Hh;
        float lo, hi;
        upk2(acc0[mp], lo, hi); G[be + h0] = lo; G[bo + h0] = hi;
        upk2(acc1[mp], lo, hi); G[be + h1] = lo; G[bo + h1] = hi;
        if (v3) { upk2(acc2[mp], lo, hi); G[be + h2] = lo; G[bo + h2] = hi; }
    }
}

// ---------------- reduce split-K partials for Y (float4) ----------------
__global__ void ypart_reduce(const float* __restrict__ part, const float* __restrict__ b2s,
                             float* __restrict__ Y)
{
    const int i4 = blockIdx.x * blockDim.x + threadIdx.x;    // Rows*OUTD/4
    const int idx = i4 * 4;
    const int col = idx & (OUTD - 1);
    float4 s = *(const float4*)(b2s + col);
    #pragma unroll
    for (int z = 0; z < YSPLIT; ++z) {
        float4 p = *(const float4*)(part + z * (Rows * OUTD) + idx);
        s.x += p.x; s.y += p.y; s.z += p.z; s.w += p.w;
    }
    *(float4*)(Y + idx) = s;
}

// ---------------- output GEMM: out[16,512] = Yflat[16,8192] @ Wout + bout ----------------
// block: 128 threads, each owns 4 consecutive cols; grid.y = OSPLIT over K
__global__ __launch_bounds__(128) void out_partial(const float* __restrict__ Y,
                                                   const float* __restrict__ Wout,
                                                   float* __restrict__ part)
{
    constexpr int KC = (Bb * Mt * Dd / Bb) / OSPLIT;   // 8192/64 = 128
    __shared__ float ys[Bb][KC];
    const int tid = threadIdx.x;
    const int col = tid * 4;
    const int k0  = blockIdx.y * KC;

    for (int idx = tid; idx < Bb * KC; idx += 128) {
        const int bi = idx / KC, kk = idx - bi * KC;
        ys[bi][kk] = Y[bi * (Mt * Dd) + k0 + kk];
    }
    __syncthreads();

    float4 acc[Bb];
    #pragma unroll
    for (int bi = 0; bi < Bb; ++bi) acc[bi] = make_float4(0.f,0.f,0.f,0.f);

    for (int kk = 0; kk < KC; ++kk) {
        const float4 w = *(const float4*)(Wout + (k0 + kk) * OUTD + col);
        #pragma unroll
        for (int bi = 0; bi < Bb; ++bi) {
            const float yv = ys[bi][kk];
            acc[bi].x = fmaf(yv, w.x, acc[bi].x);
            acc[bi].y = fmaf(yv, w.y, acc[bi].y);
            acc[bi].z = fmaf(yv, w.z, acc[bi].z);
            acc[bi].w = fmaf(yv, w.w, acc[bi].w);
        }
    }
    #pragma unroll
    for (int bi = 0; bi < Bb; ++bi)
        *(float4*)(part + (blockIdx.y * Bb + bi) * OUTD + col) = acc[bi];
}

__global__ void out_reduce(const float* __restrict__ part, const float* __restrict__ bout,
                           float* __restrict__ out)
{
    const int i4 = blockIdx.x * blockDim.x + threadIdx.x;    // Bb*OUTD/4 = 2048
    const int idx = i4 * 4;
    const int col = idx & (OUTD - 1);
    const int bi  = idx >> 9;
    float4 s = *(const float4*)(bout + col);
    #pragma unroll
    for (int z = 0; z < OSPLIT; ++z) {
        float4 p = *(const float4*)(part + (z * Bb + bi) * OUTD + col);
        s.x += p.x; s.y += p.y; s.z += p.z; s.w += p.w;
    }
    *(float4*)(out + idx) = s;
}

// ---------------- launch ----------------
extern "C" void kernel_launch(void* const* d_in, const int* in_sizes, int n_in,
                              void* d_out, int out_size)
{
    const float* x    = (const float*)d_in[0];
    const float* phi  = (const float*)d_in[1];
    const float* W1   = (const float*)d_in[2];
    const float* b1   = (const float*)d_in[3];
    const float* W2   = (const float*)d_in[4];
    const float* b2   = (const float*)d_in[5];
    const float* Wout = (const float*)d_in[6];
    const float* bout = (const float*)d_in[7];
    float* out = (float*)d_out;

    float *p_logits, *p_Dw, *p_Cw, *p_XW1, *p_G, *p_Ypart, *p_Y, *p_b2sum, *p_opart;
    cudaGetSymbolAddress((void**)&p_logits, g_logits);
    cudaGetSymbolAddress((void**)&p_Dw,     g_Dw);
    cudaGetSymbolAddress((void**)&p_Cw,     g_Cw);
    cudaGetSymbolAddress((void**)&p_XW1,    g_XW1);
    cudaGetSymbolAddress((void**)&p_G,      g_G);
    cudaGetSymbolAddress((void**)&p_Ypart,  g_Ypart);
    cudaGetSymbolAddress((void**)&p_Y,      g_Y);
    cudaGetSymbolAddress((void**)&p_b2sum,  g_b2sum);
    cudaGetSymbolAddress((void**)&p_opart,  g_opart);

    const dim3 gBig((NHt + 127) / 128, Rows / 64, 1);        // 86 x 4
    gemmT<0><<<gBig, 128>>>(x, phi, p_logits, Rows, NHt, Dd, 1);
    gemmT<1><<<gBig, 128>>>(x, W1,  p_XW1,    Rows, NHt, Dd, 1);

    softmax_m <<<(Bb * (NHt/4) + 255) / 256, 256>>>(p_logits, p_Dw);
    softmax_np<<<Rows, 256>>>(p_logits, p_Cw);
    b2sum_k   <<<(OUTD + 255) / 256, 256>>>(b2, p_b2sum);

    fused_G<<<Bb * Ne, 256>>>(p_XW1, p_Dw, p_Cw, b1, p_G);

    const dim3 gY(OUTD / 128, Rows / 64, YSPLIT);            // 4 x 4 x 16
    gemmT<0><<<gY, 128>>>(p_G, W2, p_Ypart, Rows, OUTD, NHt, YSPLIT);
    ypart_reduce<<<(Rows * OUTD / 4) / 256, 256>>>(p_Ypart, p_b2sum, p_Y);

    const dim3 gO(1, OSPLIT, 1);                             // 64 blocks
    out_partial<<<gO, 128>>>(p_Y, Wout, p_opart);
    out_reduce <<<(Bb * OUTD / 4) / 256, 256>>>(p_opart, bout, out);
}

// round 5
// speedup vs baseline: 1.3350x; 1.1074x over previous
#include <cuda_runtime.h>
#include <cuda_bf16.h>
#include <math.h>
#include <stdint.h>

#define Bb   16
#define Mt   16
#define Dd   512
#define Ne   16
#define Hh   682
#define NHt  (Ne*Hh)      /* 10912 */
#define Rows (Bb*Mt)      /* 256   */
#define OUTD 512
#define YSPLIT 16
#define OSPLIT 64

typedef unsigned long long ull;
typedef __nv_bfloat16 bf16;

// ---- packed fp32 helpers ----
__device__ __forceinline__ ull pk2(float lo, float hi) {
    ull r; asm("mov.b64 %0,{%1,%2};" : "=l"(r) : "f"(lo), "f"(hi)); return r;
}
__device__ __forceinline__ void upk2(ull v, float& lo, float& hi) {
    asm("mov.b64 {%0,%1},%2;" : "=f"(lo), "=f"(hi) : "l"(v));
}
__device__ __forceinline__ ull fma2(ull a, ull b, ull c) {
    ull d; asm("fma.rn.f32x2 %0,%1,%2,%3;" : "=l"(d) : "l"(a), "l"(b), "l"(c)); return d;
}

// ---- warp mma: D(16x8 f32) += A(16x16 bf16) * B(16x8 bf16) ----
__device__ __forceinline__ void mma_bf16(float* c, uint32_t a0, uint32_t a1, uint32_t a2, uint32_t a3,
                                         uint32_t b0, uint32_t b1) {
    asm volatile("mma.sync.aligned.m16n8k16.row.col.f32.bf16.bf16.f32 "
        "{%0,%1,%2,%3}, {%4,%5,%6,%7}, {%8,%9}, {%0,%1,%2,%3};"
        : "+f"(c[0]), "+f"(c[1]), "+f"(c[2]), "+f"(c[3])
        : "r"(a0), "r"(a1), "r"(a2), "r"(a3), "r"(b0), "r"(b1));
}

__device__ __forceinline__ void st_split(bf16* gh, bf16* gl, long long idx, float v) {
    bf16 h = __float2bfloat16(v);
    gh[idx] = h;
    gl[idx] = __float2bfloat16(v - __bfloat162float(h));
}

// ---------------- scratch ----------------
__device__ float g_logits[Rows*NHt];
__device__ float g_Dw[Rows*NHt];
__device__ float g_Cw[Rows*NHt];
__device__ float g_XW1[Rows*NHt];
__device__ float g_Ypart[YSPLIT*Rows*OUTD];
__device__ float g_Y[Rows*OUTD];
__device__ float g_b2sum[OUTD];
__device__ float g_opart[OSPLIT*Bb*OUTD];
// bf16 hi/lo operand buffers
__device__ bf16 g_xh[Rows*Dd],  g_xl[Rows*Dd];
__device__ bf16 g_phih[Dd*NHt], g_phil[Dd*NHt];
__device__ bf16 g_w1h[Dd*NHt],  g_w1l[Dd*NHt];
__device__ bf16 g_w2h[NHt*OUTD], g_w2l[NHt*OUTD];
__device__ bf16 g_gh[Rows*NHt], g_gl[Rows*NHt];

// ---------------- fp32 -> bf16 hi/lo split (float4 per thread) ----------------
__global__ void cvt_split(const float* __restrict__ src, bf16* __restrict__ hi,
                          bf16* __restrict__ lo, int n4)
{
    const int i = blockIdx.x * blockDim.x + threadIdx.x;
    if (i >= n4) return;
    const float4 v = ((const float4*)src)[i];
    bf16 h[4], l[4];
    const float vv[4] = {v.x, v.y, v.z, v.w};
    #pragma unroll
    for (int e = 0; e < 4; ++e) {
        h[e] = __float2bfloat16(vv[e]);
        l[e] = __float2bfloat16(vv[e] - __bfloat162float(h[e]));
    }
    *(ull*)(hi + i * 4) = *(const ull*)h;
    *(ull*)(lo + i * 4) = *(const ull*)l;
}

// ---------------- W1 repack+split: [N,D,H] -> bf16 hi/lo [D][N*H] ----------------
__global__ void w1_repack(const float* __restrict__ W1, bf16* __restrict__ w1h,
                          bf16* __restrict__ w1l)
{
    const int idx = blockIdx.x * blockDim.x + threadIdx.x;
    if (idx >= Ne * Dd * Hh) return;
    const int n = idx / (Dd * Hh);
    const int r = idx - n * (Dd * Hh);
    const int d = r / Hh;
    const int h = r - d * Hh;
    const float v = W1[idx];
    st_split(w1h, w1l, (long long)d * NHt + n * Hh + h, v);
}

// ---------------- mma.sync bf16-split GEMM ----------------
// C(+split-K partials) [z][256][Nc] = A[256][K] @ B[K][Nc]
// block tile 64(m) x 128(n); 8 warps (2m x 4n); warp tile 32x32; K-chunks of 64.
#define AS_STR 72   /* bf16 units, 144B row stride */
#define BS_STR 74   /* bf16 units, 148B row stride */
#define SM_AH 0
#define SM_AL (SM_AH + 64*AS_STR*2)          /* 9216  */
#define SM_BH (SM_AL + 64*AS_STR*2)          /* 18432 */
#define SM_BL (SM_BH + 128*BS_STR*2)         /* 37376 */
#define MG_SMEM (SM_BL + 128*BS_STR*2)       /* 56320 */

__global__ __launch_bounds__(256) void mma_gemm(
    const bf16* __restrict__ Ah, const bf16* __restrict__ Al,
    const bf16* __restrict__ Bh, const bf16* __restrict__ Bl,
    float* __restrict__ C, int Nc, int K, int nsplit)
{
    extern __shared__ __align__(16) char sm[];
    bf16* sAh = (bf16*)(sm + SM_AH);
    bf16* sAl = (bf16*)(sm + SM_AL);
    bf16* sBh = (bf16*)(sm + SM_BH);
    bf16* sBl = (bf16*)(sm + SM_BL);

    const int t = threadIdx.x;
    const int lane = t & 31, warp = t >> 5;
    const int wm = (warp & 1) * 32;
    const int wn = (warp >> 1) * 32;
    const int m0 = blockIdx.y * 64;
    const int j0 = blockIdx.x * 128;
    const int z  = blockIdx.z;
    const int nch = (K + 63) >> 6;
    const int c0 = (int)((long long)nch * z / nsplit);
    const int c1 = (int)((long long)nch * (z + 1) / nsplit);

    float acc[2][4][4];
    #pragma unroll
    for (int i = 0; i < 2; ++i)
        #pragma unroll
        for (int j = 0; j < 4; ++j)
            #pragma unroll
            for (int e = 0; e < 4; ++e) acc[i][j][e] = 0.f;

    const int gid = lane >> 2;            // 0..7
    const int qid = lane & 3;             // 0..3

    for (int c = c0; c < c1; ++c) {
        const int k0 = c << 6;
        __syncthreads();
        // ---- A tiles: 64 rows x 64 k, 8B per thread-slot
        #pragma unroll
        for (int it = 0; it < 4; ++it) {
            const int s = t + it * 256;
            const int kq = s & 15;                 // k-quad
            const int row = s >> 4;                // 0..63
            const int gk = k0 + kq * 4;
            const long long ga = (long long)(m0 + row) * K + gk;
            ull vh = 0, vl = 0;
            if (gk + 4 <= K) { vh = *(const ull*)(Ah + ga); vl = *(const ull*)(Al + ga); }
            *(ull*)(sAh + row * AS_STR + kq * 4) = vh;
            *(ull*)(sAl + row * AS_STR + kq * 4) = vl;
        }
        // ---- B tiles: 64 k x 128 n, transposed to [n][k]
        #pragma unroll
        for (int it = 0; it < 8; ++it) {
            const int s = t + it * 256;
            const int g = s & 31;                  // n-quad group
            const int k = s >> 5;                  // 0..63
            const int gj = j0 + g * 4;
            const int gk = k0 + k;
            ull vh = 0, vl = 0;
            if (gj + 4 <= Nc && gk < K) {
                const long long ga = (long long)gk * Nc + gj;
                vh = *(const ull*)(Bh + ga);
                vl = *(const ull*)(Bl + ga);
            }
            const bf16* ph = (const bf16*)&vh;
            const bf16* pl = (const bf16*)&vl;
            #pragma unroll
            for (int e = 0; e < 4; ++e) {
                sBh[(g * 4 + e) * BS_STR + k] = ph[e];
                sBl[(g * 4 + e) * BS_STR + k] = pl[e];
            }
        }
        __syncthreads();

        #pragma unroll
        for (int ks = 0; ks < 4; ++ks) {
            const int kcol = ks * 16 + qid * 2;
            // A fragments (hi & lo) for 2 m-tiles
            uint32_t ah[2][4], al[2][4];
            #pragma unroll
            for (int mi = 0; mi < 2; ++mi) {
                const int r = wm + mi * 16 + gid;
                ah[mi][0] = *(const uint32_t*)(sAh + r * AS_STR + kcol);
                ah[mi][1] = *(const uint32_t*)(sAh + (r + 8) * AS_STR + kcol);
                ah[mi][2] = *(const uint32_t*)(sAh + r * AS_STR + kcol + 8);
                ah[mi][3] = *(const uint32_t*)(sAh + (r + 8) * AS_STR + kcol + 8);
                al[mi][0] = *(const uint32_t*)(sAl + r * AS_STR + kcol);
                al[mi][1] = *(const uint32_t*)(sAl + (r + 8) * AS_STR + kcol);
                al[mi][2] = *(const uint32_t*)(sAl + r * AS_STR + kcol + 8);
                al[mi][3] = *(const uint32_t*)(sAl + (r + 8) * AS_STR + kcol + 8);
            }
            // B fragments (hi & lo) for 4 n-tiles
            uint32_t bh[4][2], bl[4][2];
            #pragma unroll
            for (int ni = 0; ni < 4; ++ni) {
                const int n = wn + ni * 8 + gid;
                bh[ni][0] = *(const uint32_t*)(sBh + n * BS_STR + kcol);
                bh[ni][1] = *(const uint32_t*)(sBh + n * BS_STR + kcol + 8);
                bl[ni][0] = *(const uint32_t*)(sBl + n * BS_STR + kcol);
                bl[ni][1] = *(const uint32_t*)(sBl + n * BS_STR + kcol + 8);
            }
            #pragma unroll
            for (int mi = 0; mi < 2; ++mi)
                #pragma unroll
                for (int ni = 0; ni < 4; ++ni) {
                    mma_bf16(acc[mi][ni], ah[mi][0], ah[mi][1], ah[mi][2], ah[mi][3],
                             bh[ni][0], bh[ni][1]);
                    mma_bf16(acc[mi][ni], ah[mi][0], ah[mi][1], ah[mi][2], ah[mi][3],
                             bl[ni][0], bl[ni][1]);
                    mma_bf16(acc[mi][ni], al[mi][0], al[mi][1], al[mi][2], al[mi][3],
                             bh[ni][0], bh[ni][1]);
                }
        }
    }

    // ---- epilogue
    float* Cz = C + (long long)z * Rows * Nc;
    #pragma unroll
    for (int mi = 0; mi < 2; ++mi) {
        const int r0 = m0 + wm + mi * 16 + gid;
        #pragma unroll
        for (int ni = 0; ni < 4; ++ni) {
            const int cn = j0 + wn + ni * 8 + qid * 2;
            if (cn < Nc) {
                float2 lo2 = make_float2(acc[mi][ni][0], acc[mi][ni][1]);
                float2 hi2 = make_float2(acc[mi][ni][2], acc[mi][ni][3]);
                *(float2*)(Cz + (long long)r0 * Nc + cn)       = lo2;
                *(float2*)(Cz + (long long)(r0 + 8) * Nc + cn) = hi2;
            }
        }
    }
}

// ---------------- Dw = softmax over m (axis=1), float4 over columns ----------------
__global__ void softmax_m(const float* __restrict__ L, float* __restrict__ Dw)
{
    const int idx = blockIdx.x * blockDim.x + threadIdx.x;
    if (idx >= Bb * (NHt / 4)) return;
    const int b = idx / (NHt / 4);
    const int c = (idx - b * (NHt / 4)) * 4;
    const float* base = L + b * Mt * NHt + c;

    float4 v[Mt];
    float4 mx = make_float4(-3.4e38f, -3.4e38f, -3.4e38f, -3.4e38f);
    #pragma unroll
    for (int m = 0; m < Mt; ++m) {
        v[m] = *(const float4*)(base + m * NHt);
        mx.x = fmaxf(mx.x, v[m].x); mx.y = fmaxf(mx.y, v[m].y);
        mx.z = fmaxf(mx.z, v[m].z); mx.w = fmaxf(mx.w, v[m].w);
    }
    float4 s = make_float4(0.f, 0.f, 0.f, 0.f);
    #pragma unroll
    for (int m = 0; m < Mt; ++m) {
        v[m].x = expf(v[m].x - mx.x); s.x += v[m].x;
        v[m].y = expf(v[m].y - mx.y); s.y += v[m].y;
        v[m].z = expf(v[m].z - mx.z); s.z += v[m].z;
        v[m].w = expf(v[m].w - mx.w); s.w += v[m].w;
    }
    const float4 inv = make_float4(1.f/s.x, 1.f/s.y, 1.f/s.z, 1.f/s.w);
    float* ob = Dw + b * Mt * NHt + c;
    #pragma unroll
    for (int m = 0; m < Mt; ++m) {
        float4 o = make_float4(v[m].x*inv.x, v[m].y*inv.y, v[m].z*inv.z, v[m].w*inv.w);
        *(float4*)(ob + m * NHt) = o;
    }
}

// ---------------- Cw = softmax_p( softmax_n(logits) ) ----------------
__global__ void softmax_np(const float* __restrict__ L, float* __restrict__ Cw)
{
    __shared__ float s[Ne * 688];
    const int bm  = blockIdx.x;
    const int tid = threadIdx.x;
    const float* Lrow = L + bm * NHt;

    for (int idx = tid; idx < NHt; idx += 256) {
        const int n = idx / Hh, p = idx - n * Hh;
        s[n * 688 + p] = Lrow[idx];
    }
    __syncthreads();

    for (int p = tid; p < Hh; p += 256) {
        float mx = -3.4e38f;
        #pragma unroll
        for (int n = 0; n < Ne; ++n) mx = fmaxf(mx, s[n * 688 + p]);
        float sum = 0.f;
        #pragma unroll
        for (int n = 0; n < Ne; ++n) {
            const float e = expf(s[n * 688 + p] - mx);
            s[n * 688 + p] = e;
            sum += e;
        }
        const float inv = 1.f / sum;
        #pragma unroll
        for (int n = 0; n < Ne; ++n) s[n * 688 + p] *= inv;
    }
    __syncthreads();

    const int warp = tid >> 5, lane = tid & 31;
    for (int n = warp; n < Ne; n += 8) {
        float mx = -3.4e38f;
        for (int p = lane; p < Hh; p += 32) mx = fmaxf(mx, s[n * 688 + p]);
        #pragma unroll
        for (int o = 16; o; o >>= 1) mx = fmaxf(mx, __shfl_xor_sync(0xffffffffu, mx, o));
        float sum = 0.f;
        for (int p = lane; p < Hh; p += 32) {
            const float e = expf(s[n * 688 + p] - mx);
            s[n * 688 + p] = e;
            sum += e;
        }
        #pragma unroll
        for (int o = 16; o; o >>= 1) sum += __shfl_xor_sync(0xffffffffu, sum, o);
        const float inv = 1.f / sum;
        for (int p = lane; p < Hh; p += 32)
            Cw[bm * NHt + n * Hh + p] = s[n * 688 + p] * inv;
    }
}

// ---------------- b2sum ----------------
__global__ void b2sum_k(const float* __restrict__ b2, float* __restrict__ b2s)
{
    const int d = blockIdx.x * blockDim.x + threadIdx.x;
    if (d < OUTD) {
        float s = 0.f;
        #pragma unroll
        for (int n = 0; n < Ne; ++n) s += b2[n * OUTD + d];
        b2s[d] = s;
    }
}

// ---------------- fused mix -> relu -> combine (f32x2) -> bf16 hi/lo G ----------------
__global__ __launch_bounds__(256, 2) void fused_G(const float* __restrict__ XW1,
                                                  const float* __restrict__ Dw,
                                                  const float* __restrict__ Cwp,
                                                  const float* __restrict__ b1,
                                                  bf16* __restrict__ gh,
                                                  bf16* __restrict__ gl)
{
    constexpr int PC = 128;
    __shared__ __align__(16) float ds[PC][18];
    __shared__ __align__(16) float cs[PC][18];

    const int bx = blockIdx.x;
    const int n  = bx & (Ne - 1);
    const int b  = bx >> 4;
    const int tid = threadIdx.x;

    const int h0 = tid, h1 = tid + 256, h2 = tid + 512;
    const bool v3 = (h2 < Hh);

    ull xw0p[8], xw1p[8], xw2p[8];
    #pragma unroll
    for (int mp = 0; mp < 8; ++mp) {
        const int be = ((b * Mt + 2*mp    ) * Ne + n) * Hh;
        const int bo = ((b * Mt + 2*mp + 1) * Ne + n) * Hh;
        xw0p[mp] = pk2(XW1[be + h0], XW1[bo + h0]);
        xw1p[mp] = pk2(XW1[be + h1], XW1[bo + h1]);
        xw2p[mp] = v3 ? pk2(XW1[be + h2], XW1[bo + h2]) : 0ULL;
    }
    const float bb0 = b1[n * Hh + h0];
    const float bb1 = b1[n * Hh + h1];
    const float bb2 = v3 ? b1[n * Hh + h2] : 0.f;

    ull acc0[8] = {}, acc1[8] = {}, acc2[8] = {};

    for (int p0 = 0; p0 < Hh; p0 += PC) {
        const int pc = min(PC, Hh - p0);
        __syncthreads();
        for (int idx = tid; idx < Mt * PC; idx += 256) {
            const int pp = idx & (PC - 1);
            const int m  = idx >> 7;
            if (pp < pc) {
                const int a = ((b * Mt + m) * Ne + n) * Hh + p0 + pp;
                ds[pp][m] = Dw[a];
                cs[pp][m] = Cwp[a];
            }
        }
        __syncthreads();
        for (int pp = 0; pp < pc; ++pp) {
            ull r0 = 0ULL, r1 = 0ULL, r2 = 0ULL;
            #pragma unroll
            for (int mp = 0; mp < 8; ++mp) {
                const ull dp = *(const ull*)&ds[pp][2*mp];
                r0 = fma2(dp, xw0p[mp], r0);
                r1 = fma2(dp, xw1p[mp], r1);
                r2 = fma2(dp, xw2p[mp], r2);
            }
            float lo, hi, s0, s1, s2;
            upk2(r0, lo, hi); s0 = fmaxf(lo + hi + bb0, 0.f);
            upk2(r1, lo, hi); s1 = fmaxf(lo + hi + bb1, 0.f);
            upk2(r2, lo, hi); s2 = fmaxf(lo + hi + bb2, 0.f);
            const ull s0d = pk2(s0, s0);
            const ull s1d = pk2(s1, s1);
            const ull s2d = pk2(s2, s2);
            #pragma unroll
            for (int mp = 0; mp < 8; ++mp) {
                const ull cp = *(const ull*)&cs[pp][2*mp];
                acc0[mp] = fma2(cp, s0d, acc0[mp]);
                acc1[mp] = fma2(cp, s1d, acc1[mp]);
                acc2[mp] = fma2(cp, s2d, acc2[mp]);
            }
        }
    }

    #pragma unroll
    for (int mp = 0; mp < 8; ++mp) {
        const int be = ((b * Mt + 2*mp    ) * Ne + n) * Hh;
        const int bo = ((b * Mt + 2*mp + 1) * Ne + n) * Hh;
        float lo, hi;
        upk2(acc0[mp], lo, hi); st_split(gh, gl, be + h0, lo); st_split(gh, gl, bo + h0, hi);
        upk2(acc1[mp], lo, hi); st_split(gh, gl, be + h1, lo); st_split(gh, gl, bo + h1, hi);
        if (v3) { upk2(acc2[mp], lo, hi); st_split(gh, gl, be + h2, lo); st_split(gh, gl, bo + h2, hi); }
    }
}

// ---------------- reduce split-K partials for Y (float4) ----------------
__global__ void ypart_reduce(const float* __restrict__ part, const float* __restrict__ b2s,
                             float* __restrict__ Y)
{
    const int i4 = blockIdx.x * blockDim.x + threadIdx.x;
    const int idx = i4 * 4;
    const int col = idx & (OUTD - 1);
    float4 s = *(const float4*)(b2s + col);
    #pragma unroll
    for (int z = 0; z < YSPLIT; ++z) {
        float4 p = *(const float4*)(part + z * (Rows * OUTD) + idx);
        s.x += p.x; s.y += p.y; s.z += p.z; s.w += p.w;
    }
    *(float4*)(Y + idx) = s;
}

// ---------------- output GEMM ----------------
__global__ __launch_bounds__(128) void out_partial(const float* __restrict__ Y,
                                                   const float* __restrict__ Wout,
                                                   float* __restrict__ part)
{
    constexpr int KC = (Mt * Dd) / OSPLIT;   // 128
    __shared__ float ys[Bb][KC];
    const int tid = threadIdx.x;
    const int col = tid * 4;
    const int k0  = blockIdx.y * KC;

    for (int idx = tid; idx < Bb * KC; idx += 128) {
        const int bi = idx / KC, kk = idx - bi * KC;
        ys[bi][kk] = Y[bi * (Mt * Dd) + k0 + kk];
    }
    __syncthreads();

    float4 acc[Bb];
    #pragma unroll
    for (int bi = 0; bi < Bb; ++bi) acc[bi] = make_float4(0.f,0.f,0.f,0.f);

    for (int kk = 0; kk < KC; ++kk) {
        const float4 w = *(const float4*)(Wout + (k0 + kk) * OUTD + col);
        #pragma unroll
        for (int bi = 0; bi < Bb; ++bi) {
            const float yv = ys[bi][kk];
            acc[bi].x = fmaf(yv, w.x, acc[bi].x);
            acc[bi].y = fmaf(yv, w.y, acc[bi].y);
            acc[bi].z = fmaf(yv, w.z, acc[bi].z);
            acc[bi].w = fmaf(yv, w.w, acc[bi].w);
        }
    }
    #pragma unroll
    for (int bi = 0; bi < Bb; ++bi)
        *(float4*)(part + (blockIdx.y * Bb + bi) * OUTD + col) = acc[bi];
}

__global__ void out_reduce(const float* __restrict__ part, const float* __restrict__ bout,
                           float* __restrict__ out)
{
    const int i4 = blockIdx.x * blockDim.x + threadIdx.x;
    const int idx = i4 * 4;
    const int col = idx & (OUTD - 1);
    const int bi  = idx >> 9;
    float4 s = *(const float4*)(bout + col);
    #pragma unroll
    for (int z = 0; z < OSPLIT; ++z) {
        float4 p = *(const float4*)(part + (z * Bb + bi) * OUTD + col);
        s.x += p.x; s.y += p.y; s.z += p.z; s.w += p.w;
    }
    *(float4*)(out + idx) = s;
}

// ---------------- launch ----------------
extern "C" void kernel_launch(void* const* d_in, const int* in_sizes, int n_in,
                              void* d_out, int out_size)
{
    const float* x    = (const float*)d_in[0];
    const float* phi  = (const float*)d_in[1];
    const float* W1   = (const float*)d_in[2];
    const float* b1   = (const float*)d_in[3];
    const float* W2   = (const float*)d_in[4];
    const float* b2   = (const float*)d_in[5];
    const float* Wout = (const float*)d_in[6];
    const float* bout = (const float*)d_in[7];
    float* out = (float*)d_out;

    float *p_logits, *p_Dw, *p_Cw, *p_XW1, *p_Ypart, *p_Y, *p_b2sum, *p_opart;
    bf16 *p_xh, *p_xl, *p_phih, *p_phil, *p_w1h, *p_w1l, *p_w2h, *p_w2l, *p_gh, *p_gl;
    cudaGetSymbolAddress((void**)&p_logits, g_logits);
    cudaGetSymbolAddress((void**)&p_Dw,     g_Dw);
    cudaGetSymbolAddress((void**)&p_Cw,     g_Cw);
    cudaGetSymbolAddress((void**)&p_XW1,    g_XW1);
    cudaGetSymbolAddress((void**)&p_Ypart,  g_Ypart);
    cudaGetSymbolAddress((void**)&p_Y,      g_Y);
    cudaGetSymbolAddress((void**)&p_b2sum,  g_b2sum);
    cudaGetSymbolAddress((void**)&p_opart,  g_opart);
    cudaGetSymbolAddress((void**)&p_xh,   g_xh);
    cudaGetSymbolAddress((void**)&p_xl,   g_xl);
    cudaGetSymbolAddress((void**)&p_phih, g_phih);
    cudaGetSymbolAddress((void**)&p_phil, g_phil);
    cudaGetSymbolAddress((void**)&p_w1h,  g_w1h);
    cudaGetSymbolAddress((void**)&p_w1l,  g_w1l);
    cudaGetSymbolAddress((void**)&p_w2h,  g_w2h);
    cudaGetSymbolAddress((void**)&p_w2l,  g_w2l);
    cudaGetSymbolAddress((void**)&p_gh,   g_gh);
    cudaGetSymbolAddress((void**)&p_gl,   g_gl);

    cudaFuncSetAttribute(mma_gemm, cudaFuncAttributeMaxDynamicSharedMemorySize, MG_SMEM);

    // operand conversions
    cvt_split<<<(Rows*Dd/4 + 255)/256, 256>>>(x,   p_xh,   p_xl,   Rows*Dd/4);
    cvt_split<<<(Dd*NHt/4 + 255)/256, 256>>>(phi, p_phih, p_phil, Dd*NHt/4);
    cvt_split<<<(NHt*OUTD/4 + 255)/256, 256>>>(W2, p_w2h, p_w2l, NHt*OUTD/4);
    w1_repack<<<(Ne*Dd*Hh + 255)/256, 256>>>(W1, p_w1h, p_w1l);

    const dim3 gBig((NHt + 127)/128, Rows/64, 1);            // 86 x 4
    mma_gemm<<<gBig, 256, MG_SMEM>>>(p_xh, p_xl, p_phih, p_phil, p_logits, NHt, Dd, 1);
    mma_gemm<<<gBig, 256, MG_SMEM>>>(p_xh, p_xl, p_w1h,  p_w1l,  p_XW1,    NHt, Dd, 1);

    softmax_m <<<(Bb*(NHt/4) + 255)/256, 256>>>(p_logits, p_Dw);
    softmax_np<<<Rows, 256>>>(p_logits, p_Cw);
    b2sum_k   <<<(OUTD + 255)/256, 256>>>(b2, p_b2sum);

    fused_G<<<Bb*Ne, 256>>>(p_XW1, p_Dw, p_Cw, b1, p_gh, p_gl);

    const dim3 gY(OUTD/128, Rows/64, YSPLIT);                // 4 x 4 x 16
    mma_gemm<<<gY, 256, MG_SMEM>>>(p_gh, p_gl, p_w2h, p_w2l, p_Ypart, OUTD, NHt, YSPLIT);
    ypart_reduce<<<(Rows*OUTD/4)/256, 256>>>(p_Ypart, p_b2sum, p_Y);

    const dim3 gO(1, OSPLIT, 1);
    out_partial<<<gO, 128>>>(p_Y, Wout, p_opart);
    out_reduce <<<(Bb*OUTD/4)/256, 256>>>(p_opart, bout, out);
}